// round 14
// baseline (speedup 1.0000x reference)
#include <cuda_runtime.h>
#include <cuda_bf16.h>
#include <math.h>

#define EPS 1e-5f
typedef unsigned long long u64;

#if !defined(__CUDA_ARCH__) || defined(__CUDA_ARCH_FEAT_SM103_ALL) || defined(__CUDA_ARCH_FEAT_SM100_ALL) || defined(__CUDA_ARCH_FEAT_SM101_ALL)
#define TC_OK 1
#else
#define TC_OK 0
#endif

// Scratch (device globals — no runtime allocation). ALL intermediates NHWC.
__device__ float g_bufA[(size_t)64*56*56*192];         // conv1 out (NHWC), region1 in-place
__device__ float g_bufB[(size_t)64*28*28*192];         // conv2 out (NHWC), region2 in-place
__device__ __nv_bfloat16 g_blob1[(size_t)64*27*24576]; // r1 W: per (g,kk,cc): [hi 192x64 SW128 | lo]
__device__ __nv_bfloat16 g_blob2[(size_t)16*27*24576]; // r2 likewise
__device__ __nv_bfloat16 g_blob2c[(size_t)12*24576];   // conv2 W
__device__ __nv_bfloat16 g_blob3c[(size_t)4*12*24576]; // conv3 W

__device__ __forceinline__ float gelu_exact(float x) {
    return 0.5f * x * (1.0f + erff(x * 0.70710678118654752f));
}
__device__ __forceinline__ void hl_split(float v, __nv_bfloat16& h, __nv_bfloat16& l) {
    h = __float2bfloat16(v);
    l = __float2bfloat16(v - __bfloat162float(h));
}

#if TC_OK
// ---------------- tcgen05 / TMA / mbarrier PTX helpers ----------------
__device__ __forceinline__ unsigned smem_u32(const void* p) {
    unsigned a; asm("{ .reg .u64 t; cvta.to.shared.u64 t, %1; cvt.u32.u64 %0, t; }" : "=r"(a) : "l"(p));
    return a;
}
__device__ __forceinline__ bool elect_one() {
    unsigned p;
    asm volatile("{\n\t.reg .pred P;\n\telect.sync _|P, 0xFFFFFFFF;\n\tselp.b32 %0, 1, 0, P;\n\t}" : "=r"(p));
    return p != 0;
}
__device__ __forceinline__ void tc_alloc(unsigned dst_smem, unsigned ncols) {
    asm volatile("tcgen05.alloc.cta_group::1.sync.aligned.shared::cta.b32 [%0], %1;"
                 :: "r"(dst_smem), "r"(ncols) : "memory");
}
__device__ __forceinline__ void tc_dealloc(unsigned tmem, unsigned ncols) {
    asm volatile("tcgen05.dealloc.cta_group::1.sync.aligned.b32 %0, %1;" :: "r"(tmem), "r"(ncols));
}
__device__ __forceinline__ void mbar_init(unsigned mbar, unsigned cnt) {
    asm volatile("mbarrier.init.shared.b64 [%0], %1;" :: "r"(mbar), "r"(cnt) : "memory");
}
__device__ __forceinline__ void mbar_wait(unsigned mbar, unsigned parity) {
    asm volatile(
        "{\n\t.reg .pred P;\n\t"
        "WL%=:\n\t"
        "mbarrier.try_wait.parity.shared.b64 P, [%0], %1, 0x989680;\n\t"
        "@P bra WD%=;\n\t"
        "bra WL%=;\n\t"
        "WD%=:\n\t}"
        :: "r"(mbar), "r"(parity) : "memory");
}
__device__ __forceinline__ void mbar_expect_tx(unsigned mbar, unsigned bytes) {
    asm volatile("mbarrier.arrive.expect_tx.shared.b64 _, [%0], %1;"
                 :: "r"(mbar), "r"(bytes) : "memory");
}
__device__ __forceinline__ void bulk_g2s(unsigned dst, const void* src, unsigned bytes, unsigned mbar) {
    asm volatile("cp.async.bulk.shared::cluster.global.mbarrier::complete_tx::bytes [%0], [%1], %2, [%3];"
                 :: "r"(dst), "l"(src), "r"(bytes), "r"(mbar) : "memory");
}
__device__ __forceinline__ void tc_commit(unsigned mbar) {
    asm volatile("tcgen05.commit.cta_group::1.mbarrier::arrive::one.shared::cluster.b64 [%0];"
                 :: "r"(mbar) : "memory");
}
// TS-form MMA: A operand in TMEM
__device__ __forceinline__ void mma_f16_ts(unsigned d, unsigned a, u64 bdesc, unsigned idesc, unsigned en) {
    asm volatile(
        "{\n\t.reg .pred p;\n\tsetp.ne.u32 p, %4, 0;\n\t"
        "tcgen05.mma.cta_group::1.kind::f16 [%0], [%1], %2, %3, {%5, %5, %5, %5}, p;\n\t}"
        :: "r"(d), "r"(a), "l"(bdesc), "r"(idesc), "r"(en), "r"(0u) : "memory");
}
__device__ __forceinline__ void sttm32(unsigned addr, const unsigned* r) {
    asm volatile(
        "tcgen05.st.sync.aligned.32x32b.x32.b32 [%0], "
        "{%1, %2, %3, %4, %5, %6, %7, %8, %9, %10, %11, %12, %13, %14, %15, %16, "
        " %17, %18, %19, %20, %21, %22, %23, %24, %25, %26, %27, %28, %29, %30, %31, %32};"
        :: "r"(addr),
           "r"(r[0]),  "r"(r[1]),  "r"(r[2]),  "r"(r[3]),
           "r"(r[4]),  "r"(r[5]),  "r"(r[6]),  "r"(r[7]),
           "r"(r[8]),  "r"(r[9]),  "r"(r[10]), "r"(r[11]),
           "r"(r[12]), "r"(r[13]), "r"(r[14]), "r"(r[15]),
           "r"(r[16]), "r"(r[17]), "r"(r[18]), "r"(r[19]),
           "r"(r[20]), "r"(r[21]), "r"(r[22]), "r"(r[23]),
           "r"(r[24]), "r"(r[25]), "r"(r[26]), "r"(r[27]),
           "r"(r[28]), "r"(r[29]), "r"(r[30]), "r"(r[31])
        : "memory");
}
__device__ __forceinline__ void ldtm32(unsigned* r, unsigned addr) {
    asm volatile(
        "tcgen05.ld.sync.aligned.32x32b.x32.b32 "
        "{%0, %1, %2, %3, %4, %5, %6, %7, %8, %9, %10, %11, %12, %13, %14, %15, "
        " %16, %17, %18, %19, %20, %21, %22, %23, %24, %25, %26, %27, %28, %29, %30, %31}, [%32];"
        : "=r"(r[0]),  "=r"(r[1]),  "=r"(r[2]),  "=r"(r[3]),
          "=r"(r[4]),  "=r"(r[5]),  "=r"(r[6]),  "=r"(r[7]),
          "=r"(r[8]),  "=r"(r[9]),  "=r"(r[10]), "=r"(r[11]),
          "=r"(r[12]), "=r"(r[13]), "=r"(r[14]), "=r"(r[15]),
          "=r"(r[16]), "=r"(r[17]), "=r"(r[18]), "=r"(r[19]),
          "=r"(r[20]), "=r"(r[21]), "=r"(r[22]), "=r"(r[23]),
          "=r"(r[24]), "=r"(r[25]), "=r"(r[26]), "=r"(r[27]),
          "=r"(r[28]), "=r"(r[29]), "=r"(r[30]), "=r"(r[31])
        : "r"(addr));
}
__device__ __forceinline__ void tc_wait_ld()  { asm volatile("tcgen05.wait::ld.sync.aligned;" ::: "memory"); }
__device__ __forceinline__ void tc_wait_st()  { asm volatile("tcgen05.wait::st.sync.aligned;" ::: "memory"); }
__device__ __forceinline__ void fence_before(){ asm volatile("tcgen05.fence::before_thread_sync;" ::: "memory"); }
__device__ __forceinline__ void fence_after() { asm volatile("tcgen05.fence::after_thread_sync;" ::: "memory"); }
__device__ __forceinline__ u64 make_desc(unsigned addr) {
    return ((u64)2 << 61) | ((u64)1 << 46) | ((u64)64 << 32) | ((u64)1 << 16)
         | (u64)((addr >> 4) & 0x3FFF);
}

// D in TMEM cols [0,192). A double buffer: buf s at col 256 + s*64 (hi +0, lo +32).
#define TM_D   0u
#define TM_AB(s) (256u + (unsigned)(s)*64u)
#define MMA_IDESC 0x8300490u   /* F32 accum, BF16xBF16, M=128, N=192 */

__device__ __forceinline__ void issue_mma12(unsigned tmem, unsigned abuf, u64 dBhi, bool first) {
    const u64 dBlo = dBhi + (24576 >> 4);
    const unsigned a = tmem + abuf;
    #pragma unroll
    for (int ks = 0; ks < 4; ++ks)
        mma_f16_ts(tmem + TM_D, a + ks*8,      dBhi + ks*2, MMA_IDESC, (first && ks == 0) ? 0u : 1u);
    #pragma unroll
    for (int ks = 0; ks < 4; ++ks)
        mma_f16_ts(tmem + TM_D, a + ks*8,      dBlo + ks*2, MMA_IDESC, 1u);
    #pragma unroll
    for (int ks = 0; ks < 4; ++ks)
        mma_f16_ts(tmem + TM_D, a + 32 + ks*8, dBhi + ks*2, MMA_IDESC, 1u);
}

// Pack 64 f32 -> 32 bf16x2 regs (hi if wg==0, lo if wg==1) and STTM.
__device__ __forceinline__ void pack_sttm(const float4* src, bool zero, int wg, int m, unsigned tmem_ab) {
    unsigned regs[32];
    if (!zero) {
        #pragma unroll
        for (int q = 0; q < 16; ++q) {
            float4 f = src[q];
            __nv_bfloat16 h0 = __float2bfloat16(f.x), h1 = __float2bfloat16(f.y);
            __nv_bfloat16 h2 = __float2bfloat16(f.z), h3 = __float2bfloat16(f.w);
            if (wg == 0) {
                __nv_bfloat162 p0(h0, h1), p1(h2, h3);
                regs[2*q]   = *(unsigned*)&p0;
                regs[2*q+1] = *(unsigned*)&p1;
            } else {
                __nv_bfloat162 p0(__float2bfloat16(f.x - __bfloat162float(h0)),
                                  __float2bfloat16(f.y - __bfloat162float(h1)));
                __nv_bfloat162 p1(__float2bfloat16(f.z - __bfloat162float(h2)),
                                  __float2bfloat16(f.w - __bfloat162float(h3)));
                regs[2*q]   = *(unsigned*)&p0;
                regs[2*q+1] = *(unsigned*)&p1;
            }
        }
    } else {
        #pragma unroll
        for (int q = 0; q < 32; ++q) regs[q] = 0u;
    }
    sttm32(tmem_ab + (unsigned)wg*32u + ((unsigned)(m >> 5) << 21), regs);
    tc_wait_st();
}
#endif // TC_OK

// ---------------------------------------------------------------------------
// Weight prep
// ---------------------------------------------------------------------------
__global__ void prep_region_blob(const float* __restrict__ w, __nv_bfloat16* __restrict__ blob, int total)
{
    int idx = blockIdx.x * blockDim.x + threadIdx.x;   // idx = (g*192 + co)*192 + ci
    if (idx >= total) return;
    int ci = idx % 192;
    int t  = idx / 192;
    int co = t % 192;
    int g  = t / 192;
    const float* wp = w + (size_t)idx * 9;             // contiguous 9 taps
    int cc = ci >> 6, j = ci & 63;
    int off = co*128 + j*2;
    off ^= (off >> 3) & 0x70;
    #pragma unroll
    for (int kk = 0; kk < 9; ++kk) {
        float v = wp[kk];
        __nv_bfloat16 h, l; hl_split(v, h, l);
        size_t base = ((size_t)((g*9 + kk)*3 + cc)) * 24576;
        blob[base + off/2]         = h;
        blob[base + 12288 + off/2] = l;
    }
}

// conv weights w[CO,192,2,2] -> blob[(nh*4+k)*3+cc] = [hi 192x64 SW128 | lo]
__global__ void prep_conv_blob(const float* __restrict__ w, __nv_bfloat16* __restrict__ blob, int CO, int total)
{
    int idx = blockIdx.x * blockDim.x + threadIdx.x;   // idx = (co*192 + ci)
    if (idx >= total) return;
    int ci = idx % 192;
    int co = idx / 192;
    const float* wp = w + (size_t)idx * 4;
    int cc = ci >> 6, j = ci & 63;
    int nh = co / 192, cop = co % 192;
    int off = cop*128 + j*2;
    off ^= (off >> 3) & 0x70;
    #pragma unroll
    for (int k = 0; k < 4; ++k) {
        float v = wp[k];
        __nv_bfloat16 h, l; hl_split(v, h, l);
        size_t base = ((size_t)((nh*4 + k)*3 + cc)) * 24576;
        blob[base + off/2]         = h;
        blob[base + 12288 + off/2] = l;
    }
}

// ---------------------------------------------------------------------------
// conv1: x(64,3,224,224) NCHW * w(192,3,4,4) s4 VALID -> bn -> gelu -> bufA NHWC
// ---------------------------------------------------------------------------
__global__ __launch_bounds__(192) void conv1_kernel(
    const float* __restrict__ x, const float* __restrict__ w,
    const float* __restrict__ bg, const float* __restrict__ bb,
    const float* __restrict__ bm, const float* __restrict__ bv)
{
    const int oh = blockIdx.x;
    const int b  = blockIdx.y;
    const int co = threadIdx.x;
    __shared__ float s_in[3*4*224];

    for (int i = co; i < 3*4*224; i += 192) {
        int ci = i / (4*224);
        int r  = (i / 224) & 3;
        int c  = i % 224;
        s_in[i] = x[(((size_t)b*3 + ci)*224 + (oh*4 + r))*224 + c];
    }
    float wreg[48];
    #pragma unroll
    for (int k = 0; k < 48; ++k) wreg[k] = w[co*48 + k];
    const float inv  = bg[co] * rsqrtf(bv[co] + EPS);
    const float beta = bb[co] - bm[co]*inv;
    __syncthreads();

    float* outp = &g_bufA[(((size_t)b*56 + oh)*56)*192 + co];
    for (int ow = 0; ow < 56; ++ow) {
        float acc = 0.f;
        #pragma unroll
        for (int ci = 0; ci < 3; ++ci)
            #pragma unroll
            for (int r = 0; r < 4; ++r)
                #pragma unroll
                for (int c = 0; c < 4; ++c)
                    acc = fmaf(wreg[(ci*4+r)*4+c], s_in[(ci*4+r)*224 + ow*4 + c], acc);
        outp[(size_t)ow*192] = gelu_exact(acc*inv + beta);
    }
}

// ---------------------------------------------------------------------------
// region_mma v3: TS-mode (A in TMEM, double-buffered), software-pipelined.
// smem: misc | B0 | B1 | PL (f32 planes, 2 tiles x 49 rows x 784B)
// ---------------------------------------------------------------------------
#define OF_TMEM   0
#define OF_MBAR   8
#define OF_TBAR0  16
#define OF_TBAR1  24
#define OF_INV    32
#define OF_BETA   (32 + 768)
#define OF_B0     2048
#define OF_B1     51200
#define OF_PL     100352
#define PL_RS     784
#define REGION_SMEM (100352 + 2*49*784)   /* 177184 */

__global__ __launch_bounds__(256, 1)
void region_mma(const __nv_bfloat16* __restrict__ blob,
                const float* __restrict__ bg, const float* __restrict__ bb,
                const float* __restrict__ bm, const float* __restrict__ bv,
                int H)   // 56 or 28
{
#if TC_OK
    extern __shared__ char smem[];
    float* buf = (H == 56) ? g_bufA : g_bufB;
    const int GW = H / 7;
    const int b0 = blockIdx.x * 2;
    const int g  = blockIdx.y;
    const int base_h = (g / GW) * 7;
    const int base_w = (g % GW) * 7;
    const int t = threadIdx.x, wid = t >> 5, lane = t & 31;
    const int wg = t >> 7, m = t & 127;        // wg: 0=hi 1=lo; m = A row
    const int p = m & 63, bl = m >> 6;
    const unsigned sbase = smem_u32(smem);
    const char* bsrc = (const char*)(blob + (size_t)g * 27 * 24576);

    if (wid == 0) tc_alloc(sbase + OF_TMEM, 512);

    if (t < 192) {
        int gc = g*192 + t;
        float inv = bg[gc] * rsqrtf(bv[gc] + EPS);
        ((float*)(smem + OF_INV))[t]  = inv;
        ((float*)(smem + OF_BETA))[t] = bb[gc] - bm[gc]*inv;
    }
    if (t == 0) {
        mbar_init(sbase + OF_MBAR, 1);
        mbar_init(sbase + OF_TBAR0, 1);
        mbar_init(sbase + OF_TBAR1, 1);
    }
    __syncthreads();

    if (t == 0) {
        mbar_expect_tx(sbase + OF_TBAR0, 49152);
        bulk_g2s(sbase + OF_B0, bsrc, 49152, sbase + OF_TBAR0);
    }

    // stage PL: f32 planes [bl][row(49)][ci(192)], row stride 784B
    for (int i = t; i < 2*49*192; i += 256) {
        int ci = i % 192, pr = (i/192) % 49, ib = i / (49*192);
        float v = buf[(((size_t)(b0 + ib)*H + base_h + pr/7)*H + base_w + pr%7)*192 + ci];
        *(float*)(smem + OF_PL + (ib*49 + pr)*PL_RS + ci*4) = v;
    }
    __syncthreads();

    unsigned tmem;
    asm volatile("ld.shared.b32 %0, [%1];" : "=r"(tmem) : "r"(sbase + OF_TMEM));

    const u64 dB[2] = { make_desc(sbase + OF_B0), make_desc(sbase + OF_B1) };

    // A(0) into TMEM buf 0
    {
        const int ky0 = -1, kx0 = -1;  // it=0: kk=0 -> ky=0,kx=0 -> shift -1,-1
        int oh = p/7 - 1, ow = p%7 - 1;
        bool valid = (p < 49) && (oh >= 0) && (ow >= 0);
        const float4* src = (const float4*)(smem + OF_PL + (bl*49 + (valid ? (oh*7 + ow) : 0))*PL_RS);
        pack_sttm(src, !valid, wg, m, tmem + TM_AB(0));
        (void)ky0; (void)kx0;
    }
    fence_before();
    __syncthreads();

    #pragma unroll 1
    for (int it = 0; it < 27; ++it) {
        if (it > 0) mbar_wait(sbase + OF_MBAR, (unsigned)((it - 1) & 1));
        if (t == 0 && it + 1 < 27) {
            unsigned nb = (it + 1) & 1;
            unsigned tb = sbase + (nb ? OF_TBAR1 : OF_TBAR0);
            mbar_expect_tx(tb, 49152);
            bulk_g2s(sbase + (nb ? OF_B1 : OF_B0), bsrc + (size_t)(it + 1)*49152, 49152, tb);
        }
        if (wid == 0 && elect_one()) {
            fence_after();
            mbar_wait(sbase + ((it & 1) ? OF_TBAR1 : OF_TBAR0), (unsigned)((it >> 1) & 1));
            issue_mma12(tmem, TM_AB(it & 1), dB[it & 1], it == 0);
            tc_commit(sbase + OF_MBAR);
        }
        if (it + 1 < 27) {
            // gather A(it+1) under MMA(it)
            const int nit = it + 1;
            const int kk = nit / 3, cc = nit - 3*kk;
            const int ky = kk / 3, kx = kk - 3*ky;
            int oh = p/7 + ky - 1, ow = p%7 + kx - 1;
            bool valid = (p < 49) && (oh >= 0) && (oh < 7) && (ow >= 0) && (ow < 7);
            const float4* src = (const float4*)(smem + OF_PL
                + (bl*49 + (valid ? (oh*7 + ow) : 0))*PL_RS + cc*256);
            pack_sttm(src, !valid, wg, m, tmem + TM_AB(nit & 1));
            fence_before();
        }
        __syncthreads();
    }
    mbar_wait(sbase + OF_MBAR, 0u);   // it=26: parity 0
    fence_after();

    // Epilogue: BN+GELU+residual (exact f32 residual from PL)
    if (wid < 4) {
        const int mm = wid*32 + lane, pp = mm & 63, bb2 = mm >> 6;
        const bool live = (pp < 49);
        const float* sinv  = (const float*)(smem + OF_INV);
        const float* sbeta = (const float*)(smem + OF_BETA);
        float* drow = buf + (((size_t)(b0 + bb2)*H + base_h + pp/7)*H + base_w + pp%7)*192;
        const float* res = (const float*)(smem + OF_PL + (bb2*49 + (live ? pp : 0))*PL_RS);
        #pragma unroll 1
        for (int c0 = 0; c0 < 192; c0 += 32) {
            unsigned r[32];
            ldtm32(r, tmem + TM_D + c0);
            tc_wait_ld();
            if (live) {
                #pragma unroll
                for (int q = 0; q < 8; ++q) {
                    float4 o;
                    float* ov = (float*)&o;
                    #pragma unroll
                    for (int e = 0; e < 4; ++e) {
                        int co = c0 + q*4 + e;
                        float a = __uint_as_float(r[q*4 + e]);
                        ov[e] = gelu_exact(a*sinv[co] + sbeta[co]) + res[co];
                    }
                    *(float4*)(drow + c0 + q*4) = o;
                }
            }
        }
    }
    __syncthreads();
    if (wid == 0) tc_dealloc(tmem, 512);
#endif
}

// ---------------------------------------------------------------------------
// conv_mma v2: TS-mode, A gathered from global directly into TMEM.
// smem: misc | B0 | B1 (padded to force 1 CTA/SM for TMEM)
// ---------------------------------------------------------------------------
#define CONV_SMEM 116736

template<bool GELU>
__global__ __launch_bounds__(256, 1)
void conv_mma(const __nv_bfloat16* __restrict__ blob,
              const float* __restrict__ src, float* __restrict__ dst,
              const float* __restrict__ bg, const float* __restrict__ bb,
              const float* __restrict__ bm, const float* __restrict__ bv,
              int SDIM, int ODIM, int dstStride)
{
#if TC_OK
    extern __shared__ char smem[];
    const int tile = blockIdx.x, nh = blockIdx.y;
    const int t = threadIdx.x, wid = t >> 5, lane = t & 31;
    const int wg = t >> 7, m = t & 127;
    const unsigned sbase = smem_u32(smem);
    const int SPOS = ODIM * ODIM;
    const char* bsrc = (const char*)blob + (size_t)nh * 12 * 49152;

    if (wid == 0) tc_alloc(sbase + OF_TMEM, 512);
    if (t < 192) {
        int gc = nh*192 + t;
        float inv = bg[gc] * rsqrtf(bv[gc] + EPS);
        ((float*)(smem + OF_INV))[t]  = inv;
        ((float*)(smem + OF_BETA))[t] = bb[gc] - bm[gc]*inv;
    }
    if (t == 0) {
        mbar_init(sbase + OF_MBAR, 1);
        mbar_init(sbase + OF_TBAR0, 1);
        mbar_init(sbase + OF_TBAR1, 1);
    }
    __syncthreads();
    if (t == 0) {
        mbar_expect_tx(sbase + OF_TBAR0, 49152);
        bulk_g2s(sbase + OF_B0, bsrc, 49152, sbase + OF_TBAR0);
    }

    // this thread's A-row source pixel (NHWC)
    size_t pixbase;
    {
        int pos = tile*128 + m;
        int b = pos / SPOS, q = pos - b*SPOS;
        int oh = q / ODIM, ow = q - oh*ODIM;
        pixbase = (((size_t)b*SDIM + 2*oh)*SDIM + 2*ow)*192;
    }

    unsigned tmem;
    asm volatile("ld.shared.b32 %0, [%1];" : "=r"(tmem) : "r"(sbase + OF_TMEM));
    const u64 dB[2] = { make_desc(sbase + OF_B0), make_desc(sbase + OF_B1) };

    // A(0): k=0 (r=0,c=0), cc=0
    pack_sttm((const float4*)(src + pixbase), false, wg, m, tmem + TM_AB(0));
    fence_before();
    __syncthreads();

    #pragma unroll 1
    for (int it = 0; it < 12; ++it) {
        if (it > 0) mbar_wait(sbase + OF_MBAR, (unsigned)((it - 1) & 1));
        if (t == 0 && it + 1 < 12) {
            unsigned nb = (it + 1) & 1;
            unsigned tb = sbase + (nb ? OF_TBAR1 : OF_TBAR0);
            mbar_expect_tx(tb, 49152);
            bulk_g2s(sbase + (nb ? OF_B1 : OF_B0), bsrc + (size_t)(it + 1)*49152, 49152, tb);
        }
        if (wid == 0 && elect_one()) {
            fence_after();
            mbar_wait(sbase + ((it & 1) ? OF_TBAR1 : OF_TBAR0), (unsigned)((it >> 1) & 1));
            issue_mma12(tmem, TM_AB(it & 1), dB[it & 1], it == 0);
            tc_commit(sbase + OF_MBAR);
        }
        if (it + 1 < 12) {
            const int nit = it + 1;
            const int k = nit / 3, cc = nit - 3*k;
            const int r = k >> 1, c = k & 1;
            const size_t koff = ((size_t)(r*SDIM + c))*192 + cc*64;
            pack_sttm((const float4*)(src + pixbase + koff), false, wg, m, tmem + TM_AB(nit & 1));
            fence_before();
        }
        __syncthreads();
    }
    mbar_wait(sbase + OF_MBAR, 1u);   // it=11: parity 1
    fence_after();

    if (wid < 4) {
        const int mm = wid*32 + lane;
        const int pos = tile*128 + mm;
        const float* sinv  = (const float*)(smem + OF_INV);
        const float* sbeta = (const float*)(smem + OF_BETA);
        float* drow = dst + (size_t)pos*dstStride + nh*192;
        #pragma unroll 1
        for (int c0 = 0; c0 < 192; c0 += 32) {
            unsigned r[32];
            ldtm32(r, tmem + TM_D + c0);
            tc_wait_ld();
            #pragma unroll
            for (int q = 0; q < 8; ++q) {
                float4 o;
                float* ov = (float*)&o;
                #pragma unroll
                for (int e = 0; e < 4; ++e) {
                    int co = c0 + q*4 + e;
                    float a = __uint_as_float(r[q*4 + e]);
                    float y = a*sinv[co] + sbeta[co];
                    ov[e] = GELU ? gelu_exact(y) : y;
                }
                *(float4*)(drow + c0 + q*4) = o;
            }
        }
    }
    __syncthreads();
    if (wid == 0) tc_dealloc(tmem, 512);
#endif
}

// ---------------------------------------------------------------------------
extern "C" void kernel_launch(void* const* d_in, const int* in_sizes, int n_in,
                              void* d_out, int out_size)
{
    const float* x       = (const float*)d_in[0];
    const float* c1w     = (const float*)d_in[1];
    const float* b1g = (const float*)d_in[2],  *b1b = (const float*)d_in[3];
    const float* b1m = (const float*)d_in[4],  *b1v = (const float*)d_in[5];
    const float* r1w     = (const float*)d_in[6];
    const float* r1g = (const float*)d_in[7],  *r1b = (const float*)d_in[8];
    const float* r1m = (const float*)d_in[9],  *r1v = (const float*)d_in[10];
    const float* c2w     = (const float*)d_in[11];
    const float* b2g = (const float*)d_in[12], *b2b = (const float*)d_in[13];
    const float* b2m = (const float*)d_in[14], *b2v = (const float*)d_in[15];
    const float* r2w     = (const float*)d_in[16];
    const float* r2g = (const float*)d_in[17], *r2b = (const float*)d_in[18];
    const float* r2m = (const float*)d_in[19], *r2v = (const float*)d_in[20];
    const float* c3w     = (const float*)d_in[21];
    const float* b3g = (const float*)d_in[22], *b3b = (const float*)d_in[23];
    const float* b3m = (const float*)d_in[24], *b3v = (const float*)d_in[25];
    float* out = (float*)d_out;

    __nv_bfloat16 *blob1, *blob2, *blob2c, *blob3c;
    float *bufA, *bufB;
    cudaGetSymbolAddress((void**)&blob1, g_blob1);
    cudaGetSymbolAddress((void**)&blob2, g_blob2);
    cudaGetSymbolAddress((void**)&blob2c, g_blob2c);
    cudaGetSymbolAddress((void**)&blob3c, g_blob3c);
    cudaGetSymbolAddress((void**)&bufA, g_bufA);
    cudaGetSymbolAddress((void**)&bufB, g_bufB);

    {   // weight prep
        int t1 = 64*192*192;
        prep_region_blob<<<(t1 + 255)/256, 256>>>(r1w, blob1, t1);
        int t2 = 16*192*192;
        prep_region_blob<<<(t2 + 255)/256, 256>>>(r2w, blob2, t2);
        int t3 = 192*192;
        prep_conv_blob<<<(t3 + 255)/256, 256>>>(c2w, blob2c, 192, t3);
        int t4 = 768*192;
        prep_conv_blob<<<(t4 + 255)/256, 256>>>(c3w, blob3c, 768, t4);
    }

    cudaFuncSetAttribute(region_mma, cudaFuncAttributeMaxDynamicSharedMemorySize, REGION_SMEM);
    cudaFuncSetAttribute(conv_mma<true>,  cudaFuncAttributeMaxDynamicSharedMemorySize, CONV_SMEM);
    cudaFuncSetAttribute(conv_mma<false>, cudaFuncAttributeMaxDynamicSharedMemorySize, CONV_SMEM);

    conv1_kernel<<<dim3(56, 64), 192>>>(x, c1w, b1g, b1b, b1m, b1v);
    region_mma<<<dim3(32, 64), 256, REGION_SMEM>>>(blob1, r1g, r1b, r1m, r1v, 56);
    conv_mma<true><<<dim3(392, 1), 256, CONV_SMEM>>>(blob2c, bufA, bufB,
                                                     b2g, b2b, b2m, b2v, 56, 28, 192);
    region_mma<<<dim3(32, 16), 256, REGION_SMEM>>>(blob2, r2g, r2b, r2m, r2v, 28);
    conv_mma<false><<<dim3(98, 4), 256, CONV_SMEM>>>(blob3c, bufB, out,
                                                     b3g, b3b, b3m, b3v, 28, 14, 768);
}

// round 15
// speedup vs baseline: 1.0105x; 1.0105x over previous
#include <cuda_runtime.h>
#include <cuda_bf16.h>
#include <math.h>

#define EPS 1e-5f
typedef unsigned long long u64;

#if !defined(__CUDA_ARCH__) || defined(__CUDA_ARCH_FEAT_SM103_ALL) || defined(__CUDA_ARCH_FEAT_SM100_ALL) || defined(__CUDA_ARCH_FEAT_SM101_ALL)
#define TC_OK 1
#else
#define TC_OK 0
#endif

// Scratch (device globals — no runtime allocation). ALL intermediates NHWC.
__device__ float g_bufA[(size_t)64*56*56*192];         // conv1 out (NHWC), region1 in-place
__device__ float g_bufB[(size_t)64*28*28*192];         // conv2 out (NHWC), region2 in-place
__device__ __nv_bfloat16 g_blob1[(size_t)64*27*24576]; // r1 W: per (g,kk,cc): [hi 192x64 SW128 | lo]
__device__ __nv_bfloat16 g_blob2[(size_t)16*27*24576]; // r2 likewise
__device__ __nv_bfloat16 g_blob2c[(size_t)12*24576];   // conv2 W
__device__ __nv_bfloat16 g_blob3c[(size_t)4*12*24576]; // conv3 W

__device__ __forceinline__ float gelu_exact(float x) {
    return 0.5f * x * (1.0f + erff(x * 0.70710678118654752f));
}
__device__ __forceinline__ void hl_split(float v, __nv_bfloat16& h, __nv_bfloat16& l) {
    h = __float2bfloat16(v);
    l = __float2bfloat16(v - __bfloat162float(h));
}

#if TC_OK
// ---------------- tcgen05 / TMA / mbarrier PTX helpers ----------------
__device__ __forceinline__ unsigned smem_u32(const void* p) {
    unsigned a; asm("{ .reg .u64 t; cvta.to.shared.u64 t, %1; cvt.u32.u64 %0, t; }" : "=r"(a) : "l"(p));
    return a;
}
__device__ __forceinline__ bool elect_one() {
    unsigned p;
    asm volatile("{\n\t.reg .pred P;\n\telect.sync _|P, 0xFFFFFFFF;\n\tselp.b32 %0, 1, 0, P;\n\t}" : "=r"(p));
    return p != 0;
}
__device__ __forceinline__ void tc_alloc(unsigned dst_smem, unsigned ncols) {
    asm volatile("tcgen05.alloc.cta_group::1.sync.aligned.shared::cta.b32 [%0], %1;"
                 :: "r"(dst_smem), "r"(ncols) : "memory");
}
__device__ __forceinline__ void tc_dealloc(unsigned tmem, unsigned ncols) {
    asm volatile("tcgen05.dealloc.cta_group::1.sync.aligned.b32 %0, %1;" :: "r"(tmem), "r"(ncols));
}
__device__ __forceinline__ void mbar_init(unsigned mbar, unsigned cnt) {
    asm volatile("mbarrier.init.shared.b64 [%0], %1;" :: "r"(mbar), "r"(cnt) : "memory");
}
__device__ __forceinline__ void mbar_wait(unsigned mbar, unsigned parity) {
    asm volatile(
        "{\n\t.reg .pred P;\n\t"
        "WL%=:\n\t"
        "mbarrier.try_wait.parity.shared.b64 P, [%0], %1, 0x989680;\n\t"
        "@P bra WD%=;\n\t"
        "bra WL%=;\n\t"
        "WD%=:\n\t}"
        :: "r"(mbar), "r"(parity) : "memory");
}
__device__ __forceinline__ void mbar_expect_tx(unsigned mbar, unsigned bytes) {
    asm volatile("mbarrier.arrive.expect_tx.shared.b64 _, [%0], %1;"
                 :: "r"(mbar), "r"(bytes) : "memory");
}
__device__ __forceinline__ void bulk_g2s(unsigned dst, const void* src, unsigned bytes, unsigned mbar) {
    asm volatile("cp.async.bulk.shared::cluster.global.mbarrier::complete_tx::bytes [%0], [%1], %2, [%3];"
                 :: "r"(dst), "l"(src), "r"(bytes), "r"(mbar) : "memory");
}
__device__ __forceinline__ void tc_commit(unsigned mbar) {
    asm volatile("tcgen05.commit.cta_group::1.mbarrier::arrive::one.shared::cluster.b64 [%0];"
                 :: "r"(mbar) : "memory");
}
__device__ __forceinline__ void mma_f16(unsigned d, u64 adesc, u64 bdesc, unsigned idesc, unsigned en) {
    asm volatile(
        "{\n\t.reg .pred p;\n\tsetp.ne.u32 p, %4, 0;\n\t"
        "tcgen05.mma.cta_group::1.kind::f16 [%0], %1, %2, %3, {%5, %5, %5, %5}, p;\n\t}"
        :: "r"(d), "l"(adesc), "l"(bdesc), "r"(idesc), "r"(en), "r"(0u) : "memory");
}
__device__ __forceinline__ void ldtm32(unsigned* r, unsigned addr) {
    asm volatile(
        "tcgen05.ld.sync.aligned.32x32b.x32.b32 "
        "{%0, %1, %2, %3, %4, %5, %6, %7, %8, %9, %10, %11, %12, %13, %14, %15, "
        " %16, %17, %18, %19, %20, %21, %22, %23, %24, %25, %26, %27, %28, %29, %30, %31}, [%32];"
        : "=r"(r[0]),  "=r"(r[1]),  "=r"(r[2]),  "=r"(r[3]),
          "=r"(r[4]),  "=r"(r[5]),  "=r"(r[6]),  "=r"(r[7]),
          "=r"(r[8]),  "=r"(r[9]),  "=r"(r[10]), "=r"(r[11]),
          "=r"(r[12]), "=r"(r[13]), "=r"(r[14]), "=r"(r[15]),
          "=r"(r[16]), "=r"(r[17]), "=r"(r[18]), "=r"(r[19]),
          "=r"(r[20]), "=r"(r[21]), "=r"(r[22]), "=r"(r[23]),
          "=r"(r[24]), "=r"(r[25]), "=r"(r[26]), "=r"(r[27]),
          "=r"(r[28]), "=r"(r[29]), "=r"(r[30]), "=r"(r[31])
        : "r"(addr));
}
__device__ __forceinline__ void tc_wait_ld()  { asm volatile("tcgen05.wait::ld.sync.aligned;" ::: "memory"); }
__device__ __forceinline__ u64 make_desc(unsigned addr) {
    return ((u64)2 << 61) | ((u64)1 << 46) | ((u64)64 << 32) | ((u64)1 << 16)
         | (u64)((addr >> 4) & 0x3FFF);
}

// Pack 16 f32 -> 8 hi-bf16x2 and 8 lo-bf16x2 words.
__device__ __forceinline__ void pack16(const float* v, unsigned* hi, unsigned* lo) {
    #pragma unroll
    for (int e = 0; e < 8; ++e) {
        __nv_bfloat16 h0, l0, h1, l1;
        hl_split(v[2*e],   h0, l0);
        hl_split(v[2*e+1], h1, l1);
        __nv_bfloat162 hp(h0, h1), lp(l0, l1);
        hi[e] = *(unsigned*)&hp;
        lo[e] = *(unsigned*)&lp;
    }
}
#endif // TC_OK

#define MMA_IDESC 0x8300490u   /* F32 accum, BF16xBF16, M=128, N=192 */

// ---------------------------------------------------------------------------
// Weight prep (thread-per-(co,ci): contiguous tap reads)
// ---------------------------------------------------------------------------
__global__ void prep_region_blob(const float* __restrict__ w, __nv_bfloat16* __restrict__ blob, int total)
{
    int idx = blockIdx.x * blockDim.x + threadIdx.x;   // (g*192 + co)*192 + ci
    if (idx >= total) return;
    int ci = idx % 192;
    int t  = idx / 192;
    int co = t % 192;
    int g  = t / 192;
    const float* wp = w + (size_t)idx * 9;
    int cc = ci >> 6, j = ci & 63;
    int off = co*128 + j*2;
    off ^= (off >> 3) & 0x70;
    #pragma unroll
    for (int kk = 0; kk < 9; ++kk) {
        float v = wp[kk];
        __nv_bfloat16 h, l; hl_split(v, h, l);
        size_t base = ((size_t)((g*9 + kk)*3 + cc)) * 24576;
        blob[base + off/2]         = h;
        blob[base + 12288 + off/2] = l;
    }
}

__global__ void prep_conv_blob(const float* __restrict__ w, __nv_bfloat16* __restrict__ blob, int CO, int total)
{
    int idx = blockIdx.x * blockDim.x + threadIdx.x;   // co*192 + ci
    if (idx >= total) return;
    int ci = idx % 192;
    int co = idx / 192;
    const float* wp = w + (size_t)idx * 4;
    int cc = ci >> 6, j = ci & 63;
    int nh = co / 192, cop = co % 192;
    int off = cop*128 + j*2;
    off ^= (off >> 3) & 0x70;
    #pragma unroll
    for (int k = 0; k < 4; ++k) {
        float v = wp[k];
        __nv_bfloat16 h, l; hl_split(v, h, l);
        size_t base = ((size_t)((nh*4 + k)*3 + cc)) * 24576;
        blob[base + off/2]         = h;
        blob[base + 12288 + off/2] = l;
    }
}

// ---------------------------------------------------------------------------
// conv1: x(64,3,224,224) NCHW * w(192,3,4,4) s4 VALID -> bn -> gelu -> bufA NHWC
// ---------------------------------------------------------------------------
__global__ __launch_bounds__(192) void conv1_kernel(
    const float* __restrict__ x, const float* __restrict__ w,
    const float* __restrict__ bg, const float* __restrict__ bb,
    const float* __restrict__ bm, const float* __restrict__ bv)
{
    const int oh = blockIdx.x;
    const int b  = blockIdx.y;
    const int co = threadIdx.x;
    __shared__ float s_in[3*4*224];

    for (int i = co; i < 3*4*224; i += 192) {
        int ci = i / (4*224);
        int r  = (i / 224) & 3;
        int c  = i % 224;
        s_in[i] = x[(((size_t)b*3 + ci)*224 + (oh*4 + r))*224 + c];
    }
    float wreg[48];
    #pragma unroll
    for (int k = 0; k < 48; ++k) wreg[k] = w[co*48 + k];
    const float inv  = bg[co] * rsqrtf(bv[co] + EPS);
    const float beta = bb[co] - bm[co]*inv;
    __syncthreads();

    float* outp = &g_bufA[(((size_t)b*56 + oh)*56)*192 + co];
    for (int ow = 0; ow < 56; ++ow) {
        float acc = 0.f;
        #pragma unroll
        for (int ci = 0; ci < 3; ++ci)
            #pragma unroll
            for (int r = 0; r < 4; ++r)
                #pragma unroll
                for (int c = 0; c < 4; ++c)
                    acc = fmaf(wreg[(ci*4+r)*4+c], s_in[(ci*4+r)*224 + ow*4 + c], acc);
        outp[(size_t)ow*192] = gelu_exact(acc*inv + beta);
    }
}

// ---------------------------------------------------------------------------
// region_mma v4: SS-mode, A gathered from GLOBAL (NHWC rows, L1/L2-hot),
// single-buffered TMA B, 84KB smem -> 2 CTAs/SM (cross-CTA MMA overlap).
// ---------------------------------------------------------------------------
#define OF_TMEM  0
#define OF_MBAR  8
#define OF_TBAR  16
#define OF_INV   32
#define OF_BETA  800
#define OF_AHI   2048
#define OF_ALO   18432
#define OF_B     34816
#define MMA_SMEM 83968        /* 2048 + 2*16384 + 49152 */

__global__ __launch_bounds__(256, 2)
void region_mma(const __nv_bfloat16* __restrict__ blob,
                const float* __restrict__ bg, const float* __restrict__ bb,
                const float* __restrict__ bm, const float* __restrict__ bv,
                int H)   // 56 or 28
{
#if TC_OK
    extern __shared__ char smem[];
    float* buf = (H == 56) ? g_bufA : g_bufB;
    const int GW = H / 7;
    const int b0 = blockIdx.x * 2;
    const int g  = blockIdx.y;
    const int base_h = (g / GW) * 7;
    const int base_w = (g % GW) * 7;
    const int t = threadIdx.x, wid = t >> 5, lane = t & 31;
    const unsigned sbase = smem_u32(smem);
    const char* bsrc = (const char*)(blob + (size_t)g * 27 * 24576);

    if (wid == 0) tc_alloc(sbase + OF_TMEM, 256);

    if (t < 192) {
        int gc = g*192 + t;
        float inv = bg[gc] * rsqrtf(bv[gc] + EPS);
        ((float*)(smem + OF_INV))[t]  = inv;
        ((float*)(smem + OF_BETA))[t] = bb[gc] - bm[gc]*inv;
    }
    if (t == 0) {
        mbar_init(sbase + OF_MBAR, 1);
        mbar_init(sbase + OF_TBAR, 1);
    }
    __syncthreads();

    if (t == 0) {   // B(0)
        mbar_expect_tx(sbase + OF_TBAR, 49152);
        bulk_g2s(sbase + OF_B, bsrc, 49152, sbase + OF_TBAR);
    }

    unsigned tmem;
    asm volatile("ld.shared.b32 %0, [%1];" : "=r"(tmem) : "r"(sbase + OF_TMEM));
    const u64 dBhi = make_desc(sbase + OF_B);
    const u64 dBlo = dBhi + (24576 >> 4);
    const u64 dAhi = make_desc(sbase + OF_AHI);
    const u64 dAlo = make_desc(sbase + OF_ALO);

    // per-thread gather tasks: u in [0,512): row m = u>>2, 16-ci quarter qq = u&3
    const int m_a = (t) >> 2,        qq_a = t & 3;          // task u = t
    const int m_b = (t + 256) >> 2,  qq_b = t & 3;          // task u = t + 256

    #pragma unroll 1
    for (int it = 0; it < 27; ++it) {
        if (it > 0) {
            mbar_wait(sbase + OF_MBAR, (unsigned)((it - 1) & 1));   // A + B free
            if (t == 0) {
                mbar_expect_tx(sbase + OF_TBAR, 49152);
                bulk_g2s(sbase + OF_B, bsrc + (size_t)it*49152, 49152, sbase + OF_TBAR);
            }
        }

        // gather A(it) from global NHWC (overlaps B TMA flight)
        const int kk = it / 3, cc = it - 3*kk;
        const int ky = kk / 3, kx = kk - 3*ky;
        #pragma unroll
        for (int s = 0; s < 2; ++s) {
            const int m = s ? m_b : m_a, qq = s ? qq_b : qq_a;
            const int p = m & 63, bl = m >> 6;
            const int oh = p/7 + ky - 1, ow = p%7 + kx - 1;
            const bool valid = (p < 49) && (oh >= 0) && (oh < 7) && (ow >= 0) && (ow < 7);
            float fv[16];
            if (valid) {
                const float* gp = buf + (((size_t)(b0 + bl)*H + base_h + oh)*H + base_w + ow)*192
                                + cc*64 + qq*16;
                #pragma unroll
                for (int e = 0; e < 4; ++e) *(float4*)(fv + 4*e) = *(const float4*)(gp + 4*e);
            } else {
                #pragma unroll
                for (int e = 0; e < 16; ++e) fv[e] = 0.f;
            }
            unsigned hi[8], lo[8];
            pack16(fv, hi, lo);
            int boff = m*128 + qq*32;
            unsigned s0 = boff ^ ((boff >> 3) & 0x70);
            unsigned s1 = (boff + 16) ^ (((boff + 16) >> 3) & 0x70);
            *(uint4*)(smem + OF_AHI + s0) = make_uint4(hi[0], hi[1], hi[2], hi[3]);
            *(uint4*)(smem + OF_AHI + s1) = make_uint4(hi[4], hi[5], hi[6], hi[7]);
            *(uint4*)(smem + OF_ALO + s0) = make_uint4(lo[0], lo[1], lo[2], lo[3]);
            *(uint4*)(smem + OF_ALO + s1) = make_uint4(lo[4], lo[5], lo[6], lo[7]);
        }
        asm volatile("fence.proxy.async.shared::cta;" ::: "memory");
        __syncthreads();

        if (wid == 0 && elect_one()) {
            mbar_wait(sbase + OF_TBAR, (unsigned)(it & 1));   // B(it) landed
            #pragma unroll
            for (int ks = 0; ks < 4; ++ks)
                mma_f16(tmem, dAhi + ks*2, dBhi + ks*2, MMA_IDESC, (it == 0 && ks == 0) ? 0u : 1u);
            #pragma unroll
            for (int ks = 0; ks < 4; ++ks)
                mma_f16(tmem, dAhi + ks*2, dBlo + ks*2, MMA_IDESC, 1u);
            #pragma unroll
            for (int ks = 0; ks < 4; ++ks)
                mma_f16(tmem, dAlo + ks*2, dBhi + ks*2, MMA_IDESC, 1u);
            tc_commit(sbase + OF_MBAR);
        }
        __syncthreads();
    }
    mbar_wait(sbase + OF_MBAR, 0u);   // it=26 -> parity 0
    asm volatile("tcgen05.fence::after_thread_sync;" ::: "memory");

    // Epilogue: BN+GELU+residual (residual from global, read-before-write per thread)
    if (wid < 4) {
        const int mm = wid*32 + lane, pp = mm & 63, bb2 = mm >> 6;
        const bool live = (pp < 49);
        const float* sinv  = (const float*)(smem + OF_INV);
        const float* sbeta = (const float*)(smem + OF_BETA);
        float* drow = buf + (((size_t)(b0 + bb2)*H + base_h + pp/7)*H + base_w + pp%7)*192;
        #pragma unroll 1
        for (int c0 = 0; c0 < 192; c0 += 32) {
            unsigned r[32];
            ldtm32(r, tmem + c0);
            tc_wait_ld();
            if (live) {
                #pragma unroll
                for (int q = 0; q < 8; ++q) {
                    float4 res = *(const float4*)(drow + c0 + q*4);
                    float4 o;
                    float* ov = (float*)&o;
                    const float* rv = (const float*)&res;
                    #pragma unroll
                    for (int e = 0; e < 4; ++e) {
                        int co = c0 + q*4 + e;
                        float a = __uint_as_float(r[q*4 + e]);
                        ov[e] = gelu_exact(a*sinv[co] + sbeta[co]) + rv[e];
                    }
                    *(float4*)(drow + c0 + q*4) = o;
                }
            }
        }
    }
    __syncthreads();
    if (wid == 0) tc_dealloc(tmem, 256);
#endif
}

// ---------------------------------------------------------------------------
// conv_mma v3: SS-mode, A from global, single-buffer TMA B, 2 CTAs/SM.
// ---------------------------------------------------------------------------
template<bool GELU>
__global__ __launch_bounds__(256, 2)
void conv_mma(const __nv_bfloat16* __restrict__ blob,
              const float* __restrict__ src, float* __restrict__ dst,
              const float* __restrict__ bg, const float* __restrict__ bb,
              const float* __restrict__ bm, const float* __restrict__ bv,
              int SDIM, int ODIM, int dstStride)
{
#if TC_OK
    extern __shared__ char smem[];
    const int tile = blockIdx.x, nh = blockIdx.y;
    const int t = threadIdx.x, wid = t >> 5, lane = t & 31;
    const unsigned sbase = smem_u32(smem);
    const int SPOS = ODIM * ODIM;
    const char* bsrc = (const char*)blob + (size_t)nh * 12 * 49152;

    if (wid == 0) tc_alloc(sbase + OF_TMEM, 256);
    if (t < 192) {
        int gc = nh*192 + t;
        float inv = bg[gc] * rsqrtf(bv[gc] + EPS);
        ((float*)(smem + OF_INV))[t]  = inv;
        ((float*)(smem + OF_BETA))[t] = bb[gc] - bm[gc]*inv;
    }
    if (t == 0) {
        mbar_init(sbase + OF_MBAR, 1);
        mbar_init(sbase + OF_TBAR, 1);
    }
    __syncthreads();
    if (t == 0) {
        mbar_expect_tx(sbase + OF_TBAR, 49152);
        bulk_g2s(sbase + OF_B, bsrc, 49152, sbase + OF_TBAR);
    }

    // gather tasks: rows m0 and m0+64, quarter qq
    const int m0 = t >> 2, qq = t & 3;
    size_t pixbase[2];
    unsigned sw0[2], sw1[2];
    #pragma unroll
    for (int s = 0; s < 2; ++s) {
        int m = m0 + s*64;
        int pos = tile*128 + m;
        int b = pos / SPOS, q = pos - b*SPOS;
        int oh = q / ODIM, ow = q - oh*ODIM;
        pixbase[s] = (((size_t)b*SDIM + 2*oh)*SDIM + 2*ow)*192 + qq*16;
        int boff = m*128 + qq*32;
        sw0[s] = boff ^ ((boff >> 3) & 0x70);
        sw1[s] = (boff + 16) ^ (((boff + 16) >> 3) & 0x70);
    }

    unsigned tmem;
    asm volatile("ld.shared.b32 %0, [%1];" : "=r"(tmem) : "r"(sbase + OF_TMEM));
    const u64 dBhi = make_desc(sbase + OF_B);
    const u64 dBlo = dBhi + (24576 >> 4);
    const u64 dAhi = make_desc(sbase + OF_AHI);
    const u64 dAlo = make_desc(sbase + OF_ALO);

    #pragma unroll 1
    for (int it = 0; it < 12; ++it) {
        if (it > 0) {
            mbar_wait(sbase + OF_MBAR, (unsigned)((it - 1) & 1));
            if (t == 0) {
                mbar_expect_tx(sbase + OF_TBAR, 49152);
                bulk_g2s(sbase + OF_B, bsrc + (size_t)it*49152, 49152, sbase + OF_TBAR);
            }
        }
        const int k = it / 3, cc = it - 3*k;
        const int r = k >> 1, c = k & 1;
        const size_t koff = ((size_t)(r*SDIM + c))*192 + cc*64;

        #pragma unroll
        for (int s = 0; s < 2; ++s) {
            const float* gp = src + pixbase[s] + koff;
            float fv[16];
            #pragma unroll
            for (int e = 0; e < 4; ++e) *(float4*)(fv + 4*e) = *(const float4*)(gp + 4*e);
            unsigned hi[8], lo[8];
            pack16(fv, hi, lo);
            *(uint4*)(smem + OF_AHI + sw0[s]) = make_uint4(hi[0], hi[1], hi[2], hi[3]);
            *(uint4*)(smem + OF_AHI + sw1[s]) = make_uint4(hi[4], hi[5], hi[6], hi[7]);
            *(uint4*)(smem + OF_ALO + sw0[s]) = make_uint4(lo[0], lo[1], lo[2], lo[3]);
            *(uint4*)(smem + OF_ALO + sw1[s]) = make_uint4(lo[4], lo[5], lo[6], lo[7]);
        }
        asm volatile("fence.proxy.async.shared::cta;" ::: "memory");
        __syncthreads();

        if (wid == 0 && elect_one()) {
            mbar_wait(sbase + OF_TBAR, (unsigned)(it & 1));
            #pragma unroll
            for (int ks = 0; ks < 4; ++ks)
                mma_f16(tmem, dAhi + ks*2, dBhi + ks*2, MMA_IDESC, (it == 0 && ks == 0) ? 0u : 1u);
            #pragma unroll
            for (int ks = 0; ks < 4; ++ks)
                mma_f16(tmem, dAhi + ks*2, dBlo + ks*2, MMA_IDESC, 1u);
            #pragma unroll
            for (int ks = 0; ks < 4; ++ks)
                mma_f16(tmem, dAlo + ks*2, dBhi + ks*2, MMA_IDESC, 1u);
            tc_commit(sbase + OF_MBAR);
        }
        __syncthreads();
    }
    mbar_wait(sbase + OF_MBAR, 1u);   // it=11 -> parity 1
    asm volatile("tcgen05.fence::after_thread_sync;" ::: "memory");

    if (wid < 4) {
        const int mm = wid*32 + lane;
        const int pos = tile*128 + mm;
        const float* sinv  = (const float*)(smem + OF_INV);
        const float* sbeta = (const float*)(smem + OF_BETA);
        float* drow = dst + (size_t)pos*dstStride + nh*192;
        #pragma unroll 1
        for (int c0 = 0; c0 < 192; c0 += 32) {
            unsigned r[32];
            ldtm32(r, tmem + c0);
            tc_wait_ld();
            #pragma unroll
            for (int q = 0; q < 8; ++q) {
                float4 o;
                float* ov = (float*)&o;
                #pragma unroll
                for (int e = 0; e < 4; ++e) {
                    int co = c0 + q*4 + e;
                    float a = __uint_as_float(r[q*4 + e]);
                    float y = a*sinv[co] + sbeta[co];
                    ov[e] = GELU ? gelu_exact(y) : y;
                }
                *(float4*)(drow + c0 + q*4) = o;
            }
        }
    }
    __syncthreads();
    if (wid == 0) tc_dealloc(tmem, 256);
#endif
}

// ---------------------------------------------------------------------------
extern "C" void kernel_launch(void* const* d_in, const int* in_sizes, int n_in,
                              void* d_out, int out_size)
{
    const float* x       = (const float*)d_in[0];
    const float* c1w     = (const float*)d_in[1];
    const float* b1g = (const float*)d_in[2],  *b1b = (const float*)d_in[3];
    const float* b1m = (const float*)d_in[4],  *b1v = (const float*)d_in[5];
    const float* r1w     = (const float*)d_in[6];
    const float* r1g = (const float*)d_in[7],  *r1b = (const float*)d_in[8];
    const float* r1m = (const float*)d_in[9],  *r1v = (const float*)d_in[10];
    const float* c2w     = (const float*)d_in[11];
    const float* b2g = (const float*)d_in[12], *b2b = (const float*)d_in[13];
    const float* b2m = (const float*)d_in[14], *b2v = (const float*)d_in[15];
    const float* r2w     = (const float*)d_in[16];
    const float* r2g = (const float*)d_in[17], *r2b = (const float*)d_in[18];
    const float* r2m = (const float*)d_in[19], *r2v = (const float*)d_in[20];
    const float* c3w     = (const float*)d_in[21];
    const float* b3g = (const float*)d_in[22], *b3b = (const float*)d_in[23];
    const float* b3m = (const float*)d_in[24], *b3v = (const float*)d_in[25];
    float* out = (float*)d_out;

    __nv_bfloat16 *blob1, *blob2, *blob2c, *blob3c;
    float *bufA, *bufB;
    cudaGetSymbolAddress((void**)&blob1, g_blob1);
    cudaGetSymbolAddress((void**)&blob2, g_blob2);
    cudaGetSymbolAddress((void**)&blob2c, g_blob2c);
    cudaGetSymbolAddress((void**)&blob3c, g_blob3c);
    cudaGetSymbolAddress((void**)&bufA, g_bufA);
    cudaGetSymbolAddress((void**)&bufB, g_bufB);

    {   // weight prep
        int t1 = 64*192*192;
        prep_region_blob<<<(t1 + 255)/256, 256>>>(r1w, blob1, t1);
        int t2 = 16*192*192;
        prep_region_blob<<<(t2 + 255)/256, 256>>>(r2w, blob2, t2);
        int t3 = 192*192;
        prep_conv_blob<<<(t3 + 255)/256, 256>>>(c2w, blob2c, 192, t3);
        int t4 = 768*192;
        prep_conv_blob<<<(t4 + 255)/256, 256>>>(c3w, blob3c, 768, t4);
    }

    cudaFuncSetAttribute(region_mma, cudaFuncAttributeMaxDynamicSharedMemorySize, MMA_SMEM);
    cudaFuncSetAttribute(conv_mma<true>,  cudaFuncAttributeMaxDynamicSharedMemorySize, MMA_SMEM);
    cudaFuncSetAttribute(conv_mma<false>, cudaFuncAttributeMaxDynamicSharedMemorySize, MMA_SMEM);

    conv1_kernel<<<dim3(56, 64), 192>>>(x, c1w, b1g, b1b, b1m, b1v);
    region_mma<<<dim3(32, 64), 256, MMA_SMEM>>>(blob1, r1g, r1b, r1m, r1v, 56);
    conv_mma<true><<<dim3(392, 1), 256, MMA_SMEM>>>(blob2c, bufA, bufB,
                                                    b2g, b2b, b2m, b2v, 56, 28, 192);
    region_mma<<<dim3(32, 16), 256, MMA_SMEM>>>(blob2, r2g, r2b, r2m, r2v, 28);
    conv_mma<false><<<dim3(98, 4), 256, MMA_SMEM>>>(blob3c, bufB, out,
                                                    b3g, b3b, b3m, b3v, 28, 14, 768);
}

// round 16
// speedup vs baseline: 1.3100x; 1.2964x over previous
#include <cuda_runtime.h>
#include <cuda_bf16.h>
#include <math.h>

#define EPS 1e-5f
typedef unsigned long long u64;

#if !defined(__CUDA_ARCH__) || defined(__CUDA_ARCH_FEAT_SM103_ALL) || defined(__CUDA_ARCH_FEAT_SM100_ALL) || defined(__CUDA_ARCH_FEAT_SM101_ALL)
#define TC_OK 1
#else
#define TC_OK 0
#endif

// Scratch (device globals). All intermediates stored as bf16 hi/lo plane pairs (NHWC).
__device__ __nv_bfloat16 g_Ahi[(size_t)64*56*56*192];  // conv1 out / region1 in-place
__device__ __nv_bfloat16 g_Alo[(size_t)64*56*56*192];
__device__ __nv_bfloat16 g_Bhi[(size_t)64*28*28*192];  // conv2 out / region2 in-place
__device__ __nv_bfloat16 g_Blo[(size_t)64*28*28*192];
__device__ __nv_bfloat16 g_blob1[(size_t)64*27*24576]; // r1 W per (g,kk,cc): [hi 192x64 SW128 | lo]
__device__ __nv_bfloat16 g_blob2[(size_t)16*27*24576];
__device__ __nv_bfloat16 g_blob2c[(size_t)12*24576];
__device__ __nv_bfloat16 g_blob3c[(size_t)4*12*24576];

__device__ __forceinline__ float gelu_exact(float x) {
    return 0.5f * x * (1.0f + erff(x * 0.70710678118654752f));
}
__device__ __forceinline__ void hl_split(float v, __nv_bfloat16& h, __nv_bfloat16& l) {
    h = __float2bfloat16(v);
    l = __float2bfloat16(v - __bfloat162float(h));
}

#if TC_OK
// ---------------- tcgen05 / TMA / mbarrier helpers ----------------
__device__ __forceinline__ unsigned smem_u32(const void* p) {
    unsigned a; asm("{ .reg .u64 t; cvta.to.shared.u64 t, %1; cvt.u32.u64 %0, t; }" : "=r"(a) : "l"(p));
    return a;
}
__device__ __forceinline__ bool elect_one() {
    unsigned p;
    asm volatile("{\n\t.reg .pred P;\n\telect.sync _|P, 0xFFFFFFFF;\n\tselp.b32 %0, 1, 0, P;\n\t}" : "=r"(p));
    return p != 0;
}
__device__ __forceinline__ void tc_alloc(unsigned dst_smem, unsigned ncols) {
    asm volatile("tcgen05.alloc.cta_group::1.sync.aligned.shared::cta.b32 [%0], %1;"
                 :: "r"(dst_smem), "r"(ncols) : "memory");
}
__device__ __forceinline__ void tc_dealloc(unsigned tmem, unsigned ncols) {
    asm volatile("tcgen05.dealloc.cta_group::1.sync.aligned.b32 %0, %1;" :: "r"(tmem), "r"(ncols));
}
__device__ __forceinline__ void mbar_init(unsigned mbar, unsigned cnt) {
    asm volatile("mbarrier.init.shared.b64 [%0], %1;" :: "r"(mbar), "r"(cnt) : "memory");
}
__device__ __forceinline__ void mbar_wait(unsigned mbar, unsigned parity) {
    asm volatile(
        "{\n\t.reg .pred P;\n\t"
        "WL%=:\n\t"
        "mbarrier.try_wait.parity.shared.b64 P, [%0], %1, 0x989680;\n\t"
        "@P bra WD%=;\n\t"
        "bra WL%=;\n\t"
        "WD%=:\n\t}"
        :: "r"(mbar), "r"(parity) : "memory");
}
__device__ __forceinline__ void mbar_expect_tx(unsigned mbar, unsigned bytes) {
    asm volatile("mbarrier.arrive.expect_tx.shared.b64 _, [%0], %1;"
                 :: "r"(mbar), "r"(bytes) : "memory");
}
__device__ __forceinline__ void bulk_g2s(unsigned dst, const void* src, unsigned bytes, unsigned mbar) {
    asm volatile("cp.async.bulk.shared::cluster.global.mbarrier::complete_tx::bytes [%0], [%1], %2, [%3];"
                 :: "r"(dst), "l"(src), "r"(bytes), "r"(mbar) : "memory");
}
__device__ __forceinline__ void tc_commit(unsigned mbar) {
    asm volatile("tcgen05.commit.cta_group::1.mbarrier::arrive::one.shared::cluster.b64 [%0];"
                 :: "r"(mbar) : "memory");
}
__device__ __forceinline__ void mma_f16(unsigned d, u64 adesc, u64 bdesc, unsigned idesc, unsigned en) {
    asm volatile(
        "{\n\t.reg .pred p;\n\tsetp.ne.u32 p, %4, 0;\n\t"
        "tcgen05.mma.cta_group::1.kind::f16 [%0], %1, %2, %3, {%5, %5, %5, %5}, p;\n\t}"
        :: "r"(d), "l"(adesc), "l"(bdesc), "r"(idesc), "r"(en), "r"(0u) : "memory");
}
__device__ __forceinline__ void ldtm32(unsigned* r, unsigned addr) {
    asm volatile(
        "tcgen05.ld.sync.aligned.32x32b.x32.b32 "
        "{%0, %1, %2, %3, %4, %5, %6, %7, %8, %9, %10, %11, %12, %13, %14, %15, "
        " %16, %17, %18, %19, %20, %21, %22, %23, %24, %25, %26, %27, %28, %29, %30, %31}, [%32];"
        : "=r"(r[0]),  "=r"(r[1]),  "=r"(r[2]),  "=r"(r[3]),
          "=r"(r[4]),  "=r"(r[5]),  "=r"(r[6]),  "=r"(r[7]),
          "=r"(r[8]),  "=r"(r[9]),  "=r"(r[10]), "=r"(r[11]),
          "=r"(r[12]), "=r"(r[13]), "=r"(r[14]), "=r"(r[15]),
          "=r"(r[16]), "=r"(r[17]), "=r"(r[18]), "=r"(r[19]),
          "=r"(r[20]), "=r"(r[21]), "=r"(r[22]), "=r"(r[23]),
          "=r"(r[24]), "=r"(r[25]), "=r"(r[26]), "=r"(r[27]),
          "=r"(r[28]), "=r"(r[29]), "=r"(r[30]), "=r"(r[31])
        : "r"(addr));
}
__device__ __forceinline__ void tc_wait_ld()  { asm volatile("tcgen05.wait::ld.sync.aligned;" ::: "memory"); }
__device__ __forceinline__ u64 make_desc(unsigned addr) {
    return ((u64)2 << 61) | ((u64)1 << 46) | ((u64)64 << 32) | ((u64)1 << 16)
         | (u64)((addr >> 4) & 0x3FFF);
}
#endif // TC_OK

#define MMA_IDESC 0x8300490u   /* F32 accum, BF16xBF16, M=128, N=192 */

// smem layout (both MMA kernels): misc | A0(hi|lo) | A1(hi|lo) | B0 | B1
#define OF_TMEM  0
#define OF_MB0   8
#define OF_MB1   16
#define OF_TB0   24
#define OF_TB1   32
#define OF_INV   64
#define OF_BETA  832
#define OF_A(s)  (2048 + (s)*32768)       /* hi 16KB at +0, lo 16KB at +16384 */
#define OF_BB(s) (67584 + (s)*49152)
#define MMA_SMEM 165888

#if TC_OK
__device__ __forceinline__ void issue_mma12(unsigned tmem, u64 dAhi, u64 dAlo,
                                            u64 dBhi, bool first) {
    const u64 dBlo = dBhi + (24576 >> 4);
    #pragma unroll
    for (int ks = 0; ks < 4; ++ks)
        mma_f16(tmem, dAhi + ks*2, dBhi + ks*2, MMA_IDESC, (first && ks == 0) ? 0u : 1u);
    #pragma unroll
    for (int ks = 0; ks < 4; ++ks)
        mma_f16(tmem, dAhi + ks*2, dBlo + ks*2, MMA_IDESC, 1u);
    #pragma unroll
    for (int ks = 0; ks < 4; ++ks)
        mma_f16(tmem, dAlo + ks*2, dBhi + ks*2, MMA_IDESC, 1u);
}
#endif

// ---------------------------------------------------------------------------
// Weight prep (unchanged from R13/R15 — proven)
// ---------------------------------------------------------------------------
__global__ void prep_region_blob(const float* __restrict__ w, __nv_bfloat16* __restrict__ blob, int total)
{
    int idx = blockIdx.x * blockDim.x + threadIdx.x;   // (g*192 + co)*192 + ci
    if (idx >= total) return;
    int ci = idx % 192;
    int t  = idx / 192;
    int co = t % 192;
    int g  = t / 192;
    const float* wp = w + (size_t)idx * 9;
    int cc = ci >> 6, j = ci & 63;
    int off = co*128 + j*2;
    off ^= (off >> 3) & 0x70;
    #pragma unroll
    for (int kk = 0; kk < 9; ++kk) {
        float v = wp[kk];
        __nv_bfloat16 h, l; hl_split(v, h, l);
        size_t base = ((size_t)((g*9 + kk)*3 + cc)) * 24576;
        blob[base + off/2]         = h;
        blob[base + 12288 + off/2] = l;
    }
}

__global__ void prep_conv_blob(const float* __restrict__ w, __nv_bfloat16* __restrict__ blob, int CO, int total)
{
    int idx = blockIdx.x * blockDim.x + threadIdx.x;   // co*192 + ci
    if (idx >= total) return;
    int ci = idx % 192;
    int co = idx / 192;
    const float* wp = w + (size_t)idx * 4;
    int cc = ci >> 6, j = ci & 63;
    int nh = co / 192, cop = co % 192;
    int off = cop*128 + j*2;
    off ^= (off >> 3) & 0x70;
    #pragma unroll
    for (int k = 0; k < 4; ++k) {
        float v = wp[k];
        __nv_bfloat16 h, l; hl_split(v, h, l);
        size_t base = ((size_t)((nh*4 + k)*3 + cc)) * 24576;
        blob[base + off/2]         = h;
        blob[base + 12288 + off/2] = l;
    }
}

// ---------------------------------------------------------------------------
// conv1: NCHW x -> bn -> gelu -> hi/lo planes (NHWC)
// ---------------------------------------------------------------------------
__global__ __launch_bounds__(192) void conv1_kernel(
    const float* __restrict__ x, const float* __restrict__ w,
    const float* __restrict__ bg, const float* __restrict__ bb,
    const float* __restrict__ bm, const float* __restrict__ bv)
{
    const int oh = blockIdx.x;
    const int b  = blockIdx.y;
    const int co = threadIdx.x;
    __shared__ float s_in[3*4*224];

    for (int i = co; i < 3*4*224; i += 192) {
        int ci = i / (4*224);
        int r  = (i / 224) & 3;
        int c  = i % 224;
        s_in[i] = x[(((size_t)b*3 + ci)*224 + (oh*4 + r))*224 + c];
    }
    float wreg[48];
    #pragma unroll
    for (int k = 0; k < 48; ++k) wreg[k] = w[co*48 + k];
    const float inv  = bg[co] * rsqrtf(bv[co] + EPS);
    const float beta = bb[co] - bm[co]*inv;
    __syncthreads();

    const size_t rowbase = (((size_t)b*56 + oh)*56)*192 + co;
    for (int ow = 0; ow < 56; ++ow) {
        float acc = 0.f;
        #pragma unroll
        for (int ci = 0; ci < 3; ++ci)
            #pragma unroll
            for (int r = 0; r < 4; ++r)
                #pragma unroll
                for (int c = 0; c < 4; ++c)
                    acc = fmaf(wreg[(ci*4+r)*4+c], s_in[(ci*4+r)*224 + ow*4 + c], acc);
        float y = gelu_exact(acc*inv + beta);
        __nv_bfloat16 h, l; hl_split(y, h, l);
        g_Ahi[rowbase + (size_t)ow*192] = h;
        g_Alo[rowbase + (size_t)ow*192] = l;
    }
}

// ---------------------------------------------------------------------------
// region_mma v5: SS-mode, pipelined. A double-buffered (pure bf16 copies from
// global hi/lo planes), B double-buffered TMA, dual commit mbars (2-deep).
// ---------------------------------------------------------------------------
__global__ __launch_bounds__(256, 1)
void region_mma(const __nv_bfloat16* __restrict__ blob,
                const float* __restrict__ bg, const float* __restrict__ bb,
                const float* __restrict__ bm, const float* __restrict__ bv,
                int H)   // 56 or 28
{
#if TC_OK
    extern __shared__ char smem[];
    __nv_bfloat16* hip = (H == 56) ? g_Ahi : g_Bhi;
    __nv_bfloat16* lop = (H == 56) ? g_Alo : g_Blo;
    const int GW = H / 7;
    const int b0 = blockIdx.x * 2;
    const int g  = blockIdx.y;
    const int base_h = (g / GW) * 7;
    const int base_w = (g % GW) * 7;
    const int t = threadIdx.x, wid = t >> 5, lane = t & 31;
    const unsigned sbase = smem_u32(smem);
    const char* bsrc = (const char*)(blob + (size_t)g * 27 * 24576);

    if (wid == 0) tc_alloc(sbase + OF_TMEM, 256);

    if (t < 192) {
        int gc = g*192 + t;
        float inv = bg[gc] * rsqrtf(bv[gc] + EPS);
        ((float*)(smem + OF_INV))[t]  = inv;
        ((float*)(smem + OF_BETA))[t] = bb[gc] - bm[gc]*inv;
    }
    if (t == 0) {
        mbar_init(sbase + OF_MB0, 1);
        mbar_init(sbase + OF_MB1, 1);
        mbar_init(sbase + OF_TB0, 1);
        mbar_init(sbase + OF_TB1, 1);
    }
    __syncthreads();

    if (t == 0) {   // B(0), B(1)
        mbar_expect_tx(sbase + OF_TB0, 49152);
        bulk_g2s(sbase + OF_BB(0), bsrc,         49152, sbase + OF_TB0);
        mbar_expect_tx(sbase + OF_TB1, 49152);
        bulk_g2s(sbase + OF_BB(1), bsrc + 49152, 49152, sbase + OF_TB1);
    }

    unsigned tmem;
    asm volatile("ld.shared.b32 %0, [%1];" : "=r"(tmem) : "r"(sbase + OF_TMEM));
    const u64 dAhi[2] = { make_desc(sbase + OF_A(0)),         make_desc(sbase + OF_A(1)) };
    const u64 dAlo[2] = { make_desc(sbase + OF_A(0) + 16384), make_desc(sbase + OF_A(1) + 16384) };
    const u64 dB[2]   = { make_desc(sbase + OF_BB(0)),        make_desc(sbase + OF_BB(1)) };

    // A-gather: pure copies from hi/lo planes, 8 LDG.128 + 8 STS.128 per thread
    auto gatherA = [&](int jt) {
        const int sb = jt & 1;
        const int kk = jt / 3, cc = jt - 3*kk;
        const int ky = kk / 3, kx = kk - 3*ky;
        #pragma unroll
        for (int u = t; u < 1024; u += 256) {
            int m = u >> 3, k = u & 7;     // m: A row; k: 16B granule (8 ci)
            int p = m & 63, bl = m >> 6;
            int oh = p/7 + ky - 1, ow = p%7 + kx - 1;
            uint4 vh = make_uint4(0,0,0,0), vl = make_uint4(0,0,0,0);
            if (p < 49 && oh >= 0 && oh < 7 && ow >= 0 && ow < 7) {
                size_t e = (((size_t)(b0 + bl)*H + base_h + oh)*H + base_w + ow)*192
                         + cc*64 + k*8;
                vh = *(const uint4*)(hip + e);
                vl = *(const uint4*)(lop + e);
            }
            int boff = m*128 + k*16;
            int sw = boff ^ ((boff >> 3) & 0x70);
            *(uint4*)(smem + OF_A(sb) + sw)         = vh;
            *(uint4*)(smem + OF_A(sb) + 16384 + sw) = vl;
        }
    };

    gatherA(0);
    asm volatile("fence.proxy.async.shared::cta;" ::: "memory");
    __syncthreads();

    #pragma unroll 1
    for (int it = 0; it < 27; ++it) {
        if (it >= 1) {
            // MMA(it-1) done -> A buf (it+1)&1 and B buf (it+1)&1 reusable
            mbar_wait(sbase + OF_MB0 + 8*((it - 1) & 1), (unsigned)(((it - 1) >> 1) & 1));
            if (t == 0 && it + 1 < 27) {
                unsigned nb = (it + 1) & 1;
                mbar_expect_tx(sbase + OF_TB0 + 8*nb, 49152);
                bulk_g2s(sbase + OF_BB(nb), bsrc + (size_t)(it + 1)*49152, 49152,
                         sbase + OF_TB0 + 8*nb);
            }
        }
        if (wid == 0 && elect_one()) {
            const int s = it & 1;
            mbar_wait(sbase + OF_TB0 + 8*s, (unsigned)((it >> 1) & 1));   // B(it) landed
            issue_mma12(tmem, dAhi[s], dAlo[s], dB[s], it == 0);
            tc_commit(sbase + OF_MB0 + 8*s);
        }
        if (it + 1 < 27) {
            gatherA(it + 1);                      // overlaps MMA(it)
            asm volatile("fence.proxy.async.shared::cta;" ::: "memory");
        }
        __syncthreads();
    }
    mbar_wait(sbase + OF_MB0 + 8*(26 & 1), (unsigned)((26 >> 1) & 1));    // mbar0, parity 1
    asm volatile("tcgen05.fence::after_thread_sync;" ::: "memory");

    // Epilogue: BN+GELU+residual(hi+lo); write split hi/lo back in place
    if (wid < 4) {
        const int mm = wid*32 + lane, pp = mm & 63, bb2 = mm >> 6;
        const bool live = (pp < 49);
        const float* sinv  = (const float*)(smem + OF_INV);
        const float* sbeta = (const float*)(smem + OF_BETA);
        const size_t pix = (((size_t)(b0 + bb2)*H + base_h + pp/7)*H + base_w + pp%7)*192;
        #pragma unroll 1
        for (int c0 = 0; c0 < 192; c0 += 32) {
            unsigned r[32];
            ldtm32(r, tmem + c0);
            tc_wait_ld();
            if (live) {
                #pragma unroll
                for (int q = 0; q < 4; ++q) {      // 8 channels per pack
                    uint4 rh = *(const uint4*)(hip + pix + c0 + q*8);
                    uint4 rl = *(const uint4*)(lop + pix + c0 + q*8);
                    const __nv_bfloat16* rhp = (const __nv_bfloat16*)&rh;
                    const __nv_bfloat16* rlp = (const __nv_bfloat16*)&rl;
                    uint4 oh4, ol4;
                    __nv_bfloat16* ohp = (__nv_bfloat16*)&oh4;
                    __nv_bfloat16* olp = (__nv_bfloat16*)&ol4;
                    #pragma unroll
                    for (int e = 0; e < 8; ++e) {
                        int co = c0 + q*8 + e;
                        float a = __uint_as_float(r[q*8 + e]);
                        float res = __bfloat162float(rhp[e]) + __bfloat162float(rlp[e]);
                        float y = gelu_exact(a*sinv[co] + sbeta[co]) + res;
                        hl_split(y, ohp[e], olp[e]);
                    }
                    *(uint4*)(hip + pix + c0 + q*8) = oh4;
                    *(uint4*)(lop + pix + c0 + q*8) = ol4;
                }
            }
        }
    }
    __syncthreads();
    if (wid == 0) tc_dealloc(tmem, 256);
#endif
}

// ---------------------------------------------------------------------------
// conv_mma v4: same pipeline; A rows from src hi/lo planes (all rows valid).
// GELU=true: conv2 (writes hi/lo planes). GELU=false: conv3 (writes f32 out).
// ---------------------------------------------------------------------------
template<bool GELU>
__global__ __launch_bounds__(256, 1)
void conv_mma(const __nv_bfloat16* __restrict__ blob,
              const __nv_bfloat16* __restrict__ srcHi, const __nv_bfloat16* __restrict__ srcLo,
              __nv_bfloat16* __restrict__ dstHi, __nv_bfloat16* __restrict__ dstLo,
              float* __restrict__ dstF,
              const float* __restrict__ bg, const float* __restrict__ bb,
              const float* __restrict__ bm, const float* __restrict__ bv,
              int SDIM, int ODIM, int dstStride)
{
#if TC_OK
    extern __shared__ char smem[];
    const int tile = blockIdx.x, nh = blockIdx.y;
    const int t = threadIdx.x, wid = t >> 5, lane = t & 31;
    const unsigned sbase = smem_u32(smem);
    const int SPOS = ODIM * ODIM;
    const char* bsrc = (const char*)blob + (size_t)nh * 12 * 49152;

    if (wid == 0) tc_alloc(sbase + OF_TMEM, 256);
    if (t < 192) {
        int gc = nh*192 + t;
        float inv = bg[gc] * rsqrtf(bv[gc] + EPS);
        ((float*)(smem + OF_INV))[t]  = inv;
        ((float*)(smem + OF_BETA))[t] = bb[gc] - bm[gc]*inv;
    }
    if (t == 0) {
        mbar_init(sbase + OF_MB0, 1);
        mbar_init(sbase + OF_MB1, 1);
        mbar_init(sbase + OF_TB0, 1);
        mbar_init(sbase + OF_TB1, 1);
    }
    __syncthreads();
    if (t == 0) {
        mbar_expect_tx(sbase + OF_TB0, 49152);
        bulk_g2s(sbase + OF_BB(0), bsrc,         49152, sbase + OF_TB0);
        mbar_expect_tx(sbase + OF_TB1, 49152);
        bulk_g2s(sbase + OF_BB(1), bsrc + 49152, 49152, sbase + OF_TB1);
    }

    // this thread's 4 gather rows: m = (t>>3) + {0,32,64,96}
    size_t rowbase[4];
    #pragma unroll
    for (int s = 0; s < 4; ++s) {
        int m = (t >> 3) + s*32;
        int pos = tile*128 + m;
        int b = pos / SPOS, q = pos - b*SPOS;
        int oh = q / ODIM, ow = q - oh*ODIM;
        rowbase[s] = (((size_t)b*SDIM + 2*oh)*SDIM + 2*ow)*192;
    }
    const int kgr = t & 7;   // 16B granule within 64-ci chunk

    unsigned tmem;
    asm volatile("ld.shared.b32 %0, [%1];" : "=r"(tmem) : "r"(sbase + OF_TMEM));
    const u64 dAhi[2] = { make_desc(sbase + OF_A(0)),         make_desc(sbase + OF_A(1)) };
    const u64 dAlo[2] = { make_desc(sbase + OF_A(0) + 16384), make_desc(sbase + OF_A(1) + 16384) };
    const u64 dB[2]   = { make_desc(sbase + OF_BB(0)),        make_desc(sbase + OF_BB(1)) };

    auto gatherA = [&](int jt) {
        const int sb = jt & 1;
        const int k = jt / 3, cc = jt - 3*k;
        const int r = k >> 1, c = k & 1;
        const size_t koff = ((size_t)(r*SDIM + c))*192 + cc*64 + kgr*8;
        #pragma unroll
        for (int s = 0; s < 4; ++s) {
            int m = (t >> 3) + s*32;
            size_t e = rowbase[s] + koff;
            uint4 vh = *(const uint4*)(srcHi + e);
            uint4 vl = *(const uint4*)(srcLo + e);
            int boff = m*128 + kgr*16;
            int sw = boff ^ ((boff >> 3) & 0x70);
            *(uint4*)(smem + OF_A(sb) + sw)         = vh;
            *(uint4*)(smem + OF_A(sb) + 16384 + sw) = vl;
        }
    };

    gatherA(0);
    asm volatile("fence.proxy.async.shared::cta;" ::: "memory");
    __syncthreads();

    #pragma unroll 1
    for (int it = 0; it < 12; ++it) {
        if (it >= 1) {
            mbar_wait(sbase + OF_MB0 + 8*((it - 1) & 1), (unsigned)(((it - 1) >> 1) & 1));
            if (t == 0 && it + 1 < 12) {
                unsigned nb = (it + 1) & 1;
                mbar_expect_tx(sbase + OF_TB0 + 8*nb, 49152);
                bulk_g2s(sbase + OF_BB(nb), bsrc + (size_t)(it + 1)*49152, 49152,
                         sbase + OF_TB0 + 8*nb);
            }
        }
        if (wid == 0 && elect_one()) {
            const int s = it & 1;
            mbar_wait(sbase + OF_TB0 + 8*s, (unsigned)((it >> 1) & 1));
            issue_mma12(tmem, dAhi[s], dAlo[s], dB[s], it == 0);
            tc_commit(sbase + OF_MB0 + 8*s);
        }
        if (it + 1 < 12) {
            gatherA(it + 1);
            asm volatile("fence.proxy.async.shared::cta;" ::: "memory");
        }
        __syncthreads();
    }
    mbar_wait(sbase + OF_MB0 + 8*(11 & 1), (unsigned)((11 >> 1) & 1));    // mbar1, parity 1
    asm volatile("tcgen05.fence::after_thread_sync;" ::: "memory");

    if (wid < 4) {
        const int mm = wid*32 + lane;
        const int pos = tile*128 + mm;
        const float* sinv  = (const float*)(smem + OF_INV);
        const float* sbeta = (const float*)(smem + OF_BETA);
        #pragma unroll 1
        for (int c0 = 0; c0 < 192; c0 += 32) {
            unsigned r[32];
            ldtm32(r, tmem + c0);
            tc_wait_ld();
            if (GELU) {
                const size_t pix = (size_t)pos*192;
                #pragma unroll
                for (int q = 0; q < 4; ++q) {
                    uint4 oh4, ol4;
                    __nv_bfloat16* ohp = (__nv_bfloat16*)&oh4;
                    __nv_bfloat16* olp = (__nv_bfloat16*)&ol4;
                    #pragma unroll
                    for (int e = 0; e < 8; ++e) {
                        int co = c0 + q*8 + e;
                        float a = __uint_as_float(r[q*8 + e]);
                        float y = gelu_exact(a*sinv[co] + sbeta[co]);
                        hl_split(y, ohp[e], olp[e]);
                    }
                    *(uint4*)(dstHi + pix + c0 + q*8) = oh4;
                    *(uint4*)(dstLo + pix + c0 + q*8) = ol4;
                }
            } else {
                float* drow = dstF + (size_t)pos*dstStride + nh*192;
                #pragma unroll
                for (int q = 0; q < 8; ++q) {
                    float4 o;
                    float* ov = (float*)&o;
                    #pragma unroll
                    for (int e = 0; e < 4; ++e) {
                        int co = c0 + q*4 + e;
                        float a = __uint_as_float(r[q*4 + e]);
                        ov[e] = a*sinv[co] + sbeta[co];
                    }
                    *(float4*)(drow + c0 + q*4) = o;
                }
            }
        }
    }
    __syncthreads();
    if (wid == 0) tc_dealloc(tmem, 256);
#endif
}

// ---------------------------------------------------------------------------
extern "C" void kernel_launch(void* const* d_in, const int* in_sizes, int n_in,
                              void* d_out, int out_size)
{
    const float* x       = (const float*)d_in[0];
    const float* c1w     = (const float*)d_in[1];
    const float* b1g = (const float*)d_in[2],  *b1b = (const float*)d_in[3];
    const float* b1m = (const float*)d_in[4],  *b1v = (const float*)d_in[5];
    const float* r1w     = (const float*)d_in[6];
    const float* r1g = (const float*)d_in[7],  *r1b = (const float*)d_in[8];
    const float* r1m = (const float*)d_in[9],  *r1v = (const float*)d_in[10];
    const float* c2w     = (const float*)d_in[11];
    const float* b2g = (const float*)d_in[12], *b2b = (const float*)d_in[13];
    const float* b2m = (const float*)d_in[14], *b2v = (const float*)d_in[15];
    const float* r2w     = (const float*)d_in[16];
    const float* r2g = (const float*)d_in[17], *r2b = (const float*)d_in[18];
    const float* r2m = (const float*)d_in[19], *r2v = (const float*)d_in[20];
    const float* c3w     = (const float*)d_in[21];
    const float* b3g = (const float*)d_in[22], *b3b = (const float*)d_in[23];
    const float* b3m = (const float*)d_in[24], *b3v = (const float*)d_in[25];
    float* out = (float*)d_out;

    __nv_bfloat16 *blob1, *blob2, *blob2c, *blob3c, *ahi, *alo, *bhi, *blo;
    cudaGetSymbolAddress((void**)&blob1, g_blob1);
    cudaGetSymbolAddress((void**)&blob2, g_blob2);
    cudaGetSymbolAddress((void**)&blob2c, g_blob2c);
    cudaGetSymbolAddress((void**)&blob3c, g_blob3c);
    cudaGetSymbolAddress((void**)&ahi, g_Ahi);
    cudaGetSymbolAddress((void**)&alo, g_Alo);
    cudaGetSymbolAddress((void**)&bhi, g_Bhi);
    cudaGetSymbolAddress((void**)&blo, g_Blo);

    {   // weight prep
        int t1 = 64*192*192;
        prep_region_blob<<<(t1 + 255)/256, 256>>>(r1w, blob1, t1);
        int t2 = 16*192*192;
        prep_region_blob<<<(t2 + 255)/256, 256>>>(r2w, blob2, t2);
        int t3 = 192*192;
        prep_conv_blob<<<(t3 + 255)/256, 256>>>(c2w, blob2c, 192, t3);
        int t4 = 768*192;
        prep_conv_blob<<<(t4 + 255)/256, 256>>>(c3w, blob3c, 768, t4);
    }

    cudaFuncSetAttribute(region_mma, cudaFuncAttributeMaxDynamicSharedMemorySize, MMA_SMEM);
    cudaFuncSetAttribute(conv_mma<true>,  cudaFuncAttributeMaxDynamicSharedMemorySize, MMA_SMEM);
    cudaFuncSetAttribute(conv_mma<false>, cudaFuncAttributeMaxDynamicSharedMemorySize, MMA_SMEM);

    conv1_kernel<<<dim3(56, 64), 192>>>(x, c1w, b1g, b1b, b1m, b1v);
    region_mma<<<dim3(32, 64), 256, MMA_SMEM>>>(blob1, r1g, r1b, r1m, r1v, 56);
    conv_mma<true><<<dim3(392, 1), 256, MMA_SMEM>>>(blob2c, ahi, alo, bhi, blo, nullptr,
                                                    b2g, b2b, b2m, b2v, 56, 28, 192);
    region_mma<<<dim3(32, 16), 256, MMA_SMEM>>>(blob2, r2g, r2b, r2m, r2v, 28);
    conv_mma<false><<<dim3(98, 4), 256, MMA_SMEM>>>(blob3c, bhi, blo, nullptr, nullptr, out,
                                                    b3g, b3b, b3m, b3v, 28, 14, 768);
}